// round 14
// baseline (speedup 1.0000x reference)
#include <cuda_runtime.h>
#include <cuda_fp16.h>
#include <cstdint>
#include <math.h>

#define B_    32
#define C_    64
#define HW_   64
#define NTILE 16

// ---- smem layout ----
#define XS_HSTRIDE 72                        // halves per (R,px) row (144B)
#define XS_BYTES   (6*66*XS_HSTRIDE*2)       // 57024
#define QBUF_OFF   XS_BYTES
#define QPX        132                       // padded px stride (floats)
#define QBUF_BYTES (4*64*QPX*4)              // 135168
#define SMEM_TOTAL (QBUF_OFF + QBUF_BYTES)   // 192192

// fragment-ordered B (weight) table: [warpclass 8][frag 64 = (kt*4+j)*4+ng][lane 32]
__device__ uint2 g_wfragB[8][64][32];
__device__ float g_part[B_][C_][NTILE];
__device__ int   g_count[B_];                // zero-init; self-resets each run

__device__ __forceinline__ void mma_xw(float* c, const uint4 a, const uint2 b) {
    asm volatile("mma.sync.aligned.m16n8k16.row.col.f32.f16.f16.f32 "
        "{%0,%1,%2,%3}, {%4,%5,%6,%7}, {%8,%9}, {%0,%1,%2,%3};"
        : "+f"(c[0]), "+f"(c[1]), "+f"(c[2]), "+f"(c[3])
        : "r"(a.x), "r"(a.y), "r"(a.z), "r"(a.w), "r"(b.x), "r"(b.y));
}
__device__ __forceinline__ void ldsm_x4(uint4& d, uint32_t addr) {
    asm volatile("ldmatrix.sync.aligned.m8n8.x4.shared.b16 {%0,%1,%2,%3}, [%4];"
        : "=r"(d.x), "=r"(d.y), "=r"(d.z), "=r"(d.w) : "r"(addr));
}
__device__ __forceinline__ uint32_t smem_u32(const void* p) {
    uint32_t a;
    asm("{ .reg .u64 t; cvta.to.shared.u64 t, %1; cvt.u32.u64 %0, t; }" : "=r"(a) : "l"(p));
    return a;
}

// ---- prep: w[ic][oc][kh][kw] fp32 -> B-fragment fp16 table ----
__global__ void prep_wfragB(const float* __restrict__ w) {
    int idx = blockIdx.x * 256 + threadIdx.x;            // 8*64*32 = 16384
    if (idx >= 16384) return;
    int wc = idx >> 11, f = (idx >> 5) & 63, t = idx & 31;
    int q = wc >> 1, h = wc & 1;
    int kt = f >> 4, j = (f >> 2) & 3, ng = f & 3;
    int jh = j >> 1, jw = j & 1;
    int a = q >> 1, bb = q & 1;
    int kh = a ? (jh ? 2 : 0) : (jh ? 3 : 1);
    int kw = bb ? (jw ? 2 : 0) : (jw ? 3 : 1);
    int tap = kh * 4 + kw;
    int oc = h * 32 + ng * 8 + (t >> 2);
    int k0 = kt * 16 + (t & 3) * 2;
    uint2 v;
    __half2 b0 = __floats2half2_rn(w[k0 * 1024 + oc * 16 + tap],
                                   w[(k0 + 1) * 1024 + oc * 16 + tap]);
    __half2 b1 = __floats2half2_rn(w[(k0 + 8) * 1024 + oc * 16 + tap],
                                   w[(k0 + 9) * 1024 + oc * 16 + tap]);
    v.x = *(uint32_t*)&b0;
    v.y = *(uint32_t*)&b1;
    g_wfragB[wc][f][t] = v;
}

// ---- main fused kernel (R5 config + fence-free in-kernel finalize) ----
__global__ void __launch_bounds__(256, 1)
fused_hmma_kernel(const float* __restrict__ x, const float* __restrict__ bias,
                  float* __restrict__ out)
{
    extern __shared__ char smem[];
    __half* xs   = (__half*)smem;                        // [6*66][72]
    float*  qbuf = (float*)(smem + QBUF_OFF);            // [4q][64oc][132px]
    __shared__ int s_last;
    const uint32_t xs_b = smem_u32(smem);

    const int tid  = threadIdx.x;
    const int lane = tid & 31;
    const int wid  = tid >> 5;
    const int tile = blockIdx.x;
    const int b    = blockIdx.y;
    const int pr0  = tile * 4;

    // ---- load B-fragments (weights) into registers: 64 uint2 = 128 regs ----
    uint2 Bw[64];
    #pragma unroll
    for (int f = 0; f < 64; f++) Bw[f] = g_wfragB[wid][f][lane];

    // ---- stage x slab as fp16 [R][px][ic], zero-padded borders ----
    const float* xb = x + (size_t)b * C_ * HW_ * HW_;
    for (int ri = tid; ri < 384; ri += 256) {            // 6 rows * 64 ic
        int R = ri >> 6, ic = ri & 63, ih = pr0 - 1 + R;
        __half hv[66];
        #pragma unroll
        for (int p = 0; p < 66; p++) hv[p] = __float2half(0.f);
        if (ih >= 0 && ih < HW_) {
            const float4* src = (const float4*)(xb + ((size_t)ic * HW_ + ih) * HW_);
            #pragma unroll
            for (int p = 0; p < 16; p++) {
                float4 v = src[p];
                hv[1 + 4*p] = __float2half(v.x);
                hv[2 + 4*p] = __float2half(v.y);
                hv[3 + 4*p] = __float2half(v.z);
                hv[4 + 4*p] = __float2half(v.w);
            }
        }
        #pragma unroll
        for (int p = 0; p < 66; p++)
            xs[(R * 66 + p) * XS_HSTRIDE + ic] = hv[p];
    }
    __syncthreads();

    const int q = wid >> 1, h = wid & 1;
    const int a = q >> 1, bb = q & 1;
    const int ro[2] = { a ? 2 : 1, a ? 1 : 0 };          // jh = 0,1
    const int co[2] = { bb ? 2 : 1, bb ? 1 : 0 };        // jw = 0,1

    const int mblk = (lane >> 3) & 1;
    const int kblk = lane >> 4;
    const int lrow = lane & 7;

    float bb8[8], psum8[8];
    #pragma unroll
    for (int ol = 0; ol < 8; ol++) { bb8[ol] = bias[wid * 8 + ol]; psum8[ol] = 0.f; }

    for (int hf = 0; hf < 2; hf++) {
        // ---- mainloop: 8 n-tiles of 16 px covering 2 pooled rows x 64 px ----
        #pragma unroll 2
        for (int nt = 0; nt < 8; nt++) {
            const int lr  = hf * 2 + (nt >> 2);
            const int pc0 = (nt & 3) * 16;

            uint4 Af[4][4];
            #pragma unroll
            for (int j = 0; j < 4; j++) {
                int R  = lr + ro[j >> 1];
                int px = pc0 + co[j & 1] + mblk * 8 + lrow;
                uint32_t rowbase = xs_b +
                    (((R * 66 + px) * XS_HSTRIDE) + kblk * 8) * 2;
                #pragma unroll
                for (int kt = 0; kt < 4; kt++)
                    ldsm_x4(Af[j][kt], rowbase + kt * 32);
            }

            float acc[4][4];
            #pragma unroll
            for (int ng = 0; ng < 4; ng++)
                #pragma unroll
                for (int i = 0; i < 4; i++) acc[ng][i] = 0.f;

            #pragma unroll
            for (int kt = 0; kt < 4; kt++)
                #pragma unroll
                for (int j = 0; j < 4; j++)
                    #pragma unroll
                    for (int ng = 0; ng < 4; ng++)
                        mma_xw(acc[ng], Af[j][kt], Bw[(kt * 4 + j) * 4 + ng]);

            int pxh = (nt >> 2) * 64 + pc0 + (lane >> 2);
            int ocb = h * 32 + 2 * (lane & 3);
            #pragma unroll
            for (int ng = 0; ng < 4; ng++) {
                float* d = qbuf + (q * 64 + ocb + ng * 8) * QPX + pxh;
                d[0]       = acc[ng][0];
                d[QPX]     = acc[ng][1];
                d[8]       = acc[ng][2];
                d[QPX + 8] = acc[ng][3];
            }
        }
        __syncthreads();

        // ---- epilogue: warp w owns oc rows w*8..w*8+7; lane reads px lane*4..+3 ----
        #pragma unroll
        for (int ol = 0; ol < 8; ol++) {
            int oc = wid * 8 + ol;
            const float* base = qbuf + oc * QPX + lane * 4;
            float4 v0 = *(const float4*)(base + 0 * 64 * QPX);
            float4 v1 = *(const float4*)(base + 1 * 64 * QPX);
            float4 v2 = *(const float4*)(base + 2 * 64 * QPX);
            float4 v3 = *(const float4*)(base + 3 * 64 * QPX);
            float m, s = 0.f;
            m = fmaxf(fmaxf(v0.x, v1.x), fmaxf(v2.x, v3.x)) + bb8[ol];
            s += fminf(fmaxf(m, -1.f), 1.f);
            m = fmaxf(fmaxf(v0.y, v1.y), fmaxf(v2.y, v3.y)) + bb8[ol];
            s += fminf(fmaxf(m, -1.f), 1.f);
            m = fmaxf(fmaxf(v0.z, v1.z), fmaxf(v2.z, v3.z)) + bb8[ol];
            s += fminf(fmaxf(m, -1.f), 1.f);
            m = fmaxf(fmaxf(v0.w, v1.w), fmaxf(v2.w, v3.w)) + bb8[ol];
            s += fminf(fmaxf(m, -1.f), 1.f);
            psum8[ol] += s;
        }
        __syncthreads();
    }

    // ---- per-tile reduction: reuse qbuf as scratch [64 oc][32 lanes] ----
    float* red2 = qbuf;
    #pragma unroll
    for (int ol = 0; ol < 8; ol++)
        red2[(wid * 8 + ol) * 32 + lane] = psum8[ol];
    __syncthreads();
    if (tid < 64) {
        const float4* r = (const float4*)(red2 + tid * 32);
        float4 s4 = make_float4(0.f, 0.f, 0.f, 0.f);
        #pragma unroll
        for (int k = 0; k < 8; k++) {
            float4 v = r[k];
            s4.x += v.x; s4.y += v.y; s4.z += v.z; s4.w += v.w;
        }
        float v = (s4.x + s4.y) + (s4.z + s4.w);
        asm volatile("st.global.cg.f32 [%0], %1;"
                     :: "l"(&g_part[b][tid][tile]), "f"(v) : "memory");
    }
    __syncthreads();

    // ---- last-CTA finalize: acq_rel atomic (no L1 flush), ld.cg reads ----
    if (tid == 0) {
        int old;
        asm volatile("atom.acq_rel.gpu.global.add.s32 %0, [%1], %2;"
                     : "=r"(old) : "l"(&g_count[b]), "r"(1) : "memory");
        s_last = (old == NTILE - 1);
    }
    __syncthreads();
    if (s_last) {
        if (tid < 64) {
            float s = 0.f;
            #pragma unroll
            for (int t = 0; t < NTILE; ++t)
                s += __ldcg(&g_part[b][tid][t]);
            out[b * C_ + tid] = tanhf(s * (1.0f / 4096.0f));
        }
        if (tid == 0) {
            int zero = 0;
            asm volatile("st.global.cg.s32 [%0], %1;" :: "l"(&g_count[b]), "r"(zero) : "memory");
        }
    }
}

extern "C" void kernel_launch(void* const* d_in, const int* in_sizes, int n_in,
                              void* d_out, int out_size)
{
    const float* x    = (const float*)d_in[0];
    const float* w    = (const float*)d_in[1];
    const float* bias = (const float*)d_in[2];
    float* out = (float*)d_out;

    cudaFuncSetAttribute(fused_hmma_kernel,
                         cudaFuncAttributeMaxDynamicSharedMemorySize, SMEM_TOTAL);

    prep_wfragB<<<64, 256>>>(w);
    fused_hmma_kernel<<<dim3(NTILE, B_), 256, SMEM_TOTAL>>>(x, bias, out);
}

// round 15
// speedup vs baseline: 1.0004x; 1.0004x over previous
#include <cuda_runtime.h>
#include <cuda_fp16.h>
#include <cstdint>
#include <math.h>

#define B_    32
#define C_    64
#define HW_   64
#define NTILE 16

// ---- smem layout ----
#define XS_HSTRIDE 72                        // halves per (R,px) row (144B)
#define XS_BYTES   (6*66*XS_HSTRIDE*2)       // 57024
#define QBUF_OFF   XS_BYTES
#define QPX        132                       // padded px stride (floats)
#define QBUF_BYTES (4*64*QPX*4)              // 135168
#define SMEM_TOTAL (QBUF_OFF + QBUF_BYTES)   // 192192

// fragment-ordered B (weight) table: [warpclass 8][frag 64 = (kt*4+j)*4+ng][lane 32]
__device__ uint2 g_wfragB[8][64][32];
__device__ float g_part[B_][C_][NTILE];
__device__ int   g_count[B_];                // zero-init; self-resets each run

__device__ __forceinline__ void mma_xw(float* c, const uint4 a, const uint2 b) {
    asm volatile("mma.sync.aligned.m16n8k16.row.col.f32.f16.f16.f32 "
        "{%0,%1,%2,%3}, {%4,%5,%6,%7}, {%8,%9}, {%0,%1,%2,%3};"
        : "+f"(c[0]), "+f"(c[1]), "+f"(c[2]), "+f"(c[3])
        : "r"(a.x), "r"(a.y), "r"(a.z), "r"(a.w), "r"(b.x), "r"(b.y));
}
__device__ __forceinline__ void ldsm_x4(uint4& d, uint32_t addr) {
    asm volatile("ldmatrix.sync.aligned.m8n8.x4.shared.b16 {%0,%1,%2,%3}, [%4];"
        : "=r"(d.x), "=r"(d.y), "=r"(d.z), "=r"(d.w) : "r"(addr));
}
__device__ __forceinline__ uint32_t smem_u32(const void* p) {
    uint32_t a;
    asm("{ .reg .u64 t; cvta.to.shared.u64 t, %1; cvt.u32.u64 %0, t; }" : "=r"(a) : "l"(p));
    return a;
}

// ---- prep: w[ic][oc][kh][kw] fp32 -> B-fragment fp16 table ----
__global__ void prep_wfragB(const float* __restrict__ w) {
    int idx = blockIdx.x * 256 + threadIdx.x;            // 8*64*32 = 16384
    if (idx >= 16384) return;
    int wc = idx >> 11, f = (idx >> 5) & 63, t = idx & 31;
    int q = wc >> 1, h = wc & 1;
    int kt = f >> 4, j = (f >> 2) & 3, ng = f & 3;
    int jh = j >> 1, jw = j & 1;
    int a = q >> 1, bb = q & 1;
    int kh = a ? (jh ? 2 : 0) : (jh ? 3 : 1);
    int kw = bb ? (jw ? 2 : 0) : (jw ? 3 : 1);
    int tap = kh * 4 + kw;
    int oc = h * 32 + ng * 8 + (t >> 2);
    int k0 = kt * 16 + (t & 3) * 2;
    uint2 v;
    __half2 b0 = __floats2half2_rn(w[k0 * 1024 + oc * 16 + tap],
                                   w[(k0 + 1) * 1024 + oc * 16 + tap]);
    __half2 b1 = __floats2half2_rn(w[(k0 + 8) * 1024 + oc * 16 + tap],
                                   w[(k0 + 9) * 1024 + oc * 16 + tap]);
    v.x = *(uint32_t*)&b0;
    v.y = *(uint32_t*)&b1;
    g_wfragB[wc][f][t] = v;
}

// ---- main fused kernel (R5 config + fence-free in-kernel finalize) ----
__global__ void __launch_bounds__(256, 1)
fused_hmma_kernel(const float* __restrict__ x, const float* __restrict__ bias,
                  float* __restrict__ out)
{
    extern __shared__ char smem[];
    __half* xs   = (__half*)smem;                        // [6*66][72]
    float*  qbuf = (float*)(smem + QBUF_OFF);            // [4q][64oc][132px]
    __shared__ int s_last;
    const uint32_t xs_b = smem_u32(smem);

    const int tid  = threadIdx.x;
    const int lane = tid & 31;
    const int wid  = tid >> 5;
    const int tile = blockIdx.x;
    const int b    = blockIdx.y;
    const int pr0  = tile * 4;

    // ---- load B-fragments (weights) into registers: 64 uint2 = 128 regs ----
    uint2 Bw[64];
    #pragma unroll
    for (int f = 0; f < 64; f++) Bw[f] = g_wfragB[wid][f][lane];

    // ---- stage x slab as fp16 [R][px][ic], zero-padded borders ----
    const float* xb = x + (size_t)b * C_ * HW_ * HW_;
    for (int ri = tid; ri < 384; ri += 256) {            // 6 rows * 64 ic
        int R = ri >> 6, ic = ri & 63, ih = pr0 - 1 + R;
        __half hv[66];
        #pragma unroll
        for (int p = 0; p < 66; p++) hv[p] = __float2half(0.f);
        if (ih >= 0 && ih < HW_) {
            const float4* src = (const float4*)(xb + ((size_t)ic * HW_ + ih) * HW_);
            #pragma unroll
            for (int p = 0; p < 16; p++) {
                float4 v = src[p];
                hv[1 + 4*p] = __float2half(v.x);
                hv[2 + 4*p] = __float2half(v.y);
                hv[3 + 4*p] = __float2half(v.z);
                hv[4 + 4*p] = __float2half(v.w);
            }
        }
        #pragma unroll
        for (int p = 0; p < 66; p++)
            xs[(R * 66 + p) * XS_HSTRIDE + ic] = hv[p];
    }
    __syncthreads();

    const int q = wid >> 1, h = wid & 1;
    const int a = q >> 1, bb = q & 1;
    const int ro[2] = { a ? 2 : 1, a ? 1 : 0 };          // jh = 0,1
    const int co[2] = { bb ? 2 : 1, bb ? 1 : 0 };        // jw = 0,1

    const int mblk = (lane >> 3) & 1;
    const int kblk = lane >> 4;
    const int lrow = lane & 7;

    float bb8[8], psum8[8];
    #pragma unroll
    for (int ol = 0; ol < 8; ol++) { bb8[ol] = bias[wid * 8 + ol]; psum8[ol] = 0.f; }

    for (int hf = 0; hf < 2; hf++) {
        // ---- mainloop: 8 n-tiles of 16 px covering 2 pooled rows x 64 px ----
        #pragma unroll 2
        for (int nt = 0; nt < 8; nt++) {
            const int lr  = hf * 2 + (nt >> 2);
            const int pc0 = (nt & 3) * 16;

            uint4 Af[4][4];
            #pragma unroll
            for (int j = 0; j < 4; j++) {
                int R  = lr + ro[j >> 1];
                int px = pc0 + co[j & 1] + mblk * 8 + lrow;
                uint32_t rowbase = xs_b +
                    (((R * 66 + px) * XS_HSTRIDE) + kblk * 8) * 2;
                #pragma unroll
                for (int kt = 0; kt < 4; kt++)
                    ldsm_x4(Af[j][kt], rowbase + kt * 32);
            }

            float acc[4][4];
            #pragma unroll
            for (int ng = 0; ng < 4; ng++)
                #pragma unroll
                for (int i = 0; i < 4; i++) acc[ng][i] = 0.f;

            #pragma unroll
            for (int kt = 0; kt < 4; kt++)
                #pragma unroll
                for (int j = 0; j < 4; j++)
                    #pragma unroll
                    for (int ng = 0; ng < 4; ng++)
                        mma_xw(acc[ng], Af[j][kt], Bw[(kt * 4 + j) * 4 + ng]);

            int pxh = (nt >> 2) * 64 + pc0 + (lane >> 2);
            int ocb = h * 32 + 2 * (lane & 3);
            #pragma unroll
            for (int ng = 0; ng < 4; ng++) {
                float* d = qbuf + (q * 64 + ocb + ng * 8) * QPX + pxh;
                d[0]       = acc[ng][0];
                d[QPX]     = acc[ng][1];
                d[8]       = acc[ng][2];
                d[QPX + 8] = acc[ng][3];
            }
        }
        __syncthreads();

        // ---- epilogue: warp w owns oc rows w*8..w*8+7; lane reads px lane*4..+3 ----
        #pragma unroll
        for (int ol = 0; ol < 8; ol++) {
            int oc = wid * 8 + ol;
            const float* base = qbuf + oc * QPX + lane * 4;
            float4 v0 = *(const float4*)(base + 0 * 64 * QPX);
            float4 v1 = *(const float4*)(base + 1 * 64 * QPX);
            float4 v2 = *(const float4*)(base + 2 * 64 * QPX);
            float4 v3 = *(const float4*)(base + 3 * 64 * QPX);
            float m, s = 0.f;
            m = fmaxf(fmaxf(v0.x, v1.x), fmaxf(v2.x, v3.x)) + bb8[ol];
            s += fminf(fmaxf(m, -1.f), 1.f);
            m = fmaxf(fmaxf(v0.y, v1.y), fmaxf(v2.y, v3.y)) + bb8[ol];
            s += fminf(fmaxf(m, -1.f), 1.f);
            m = fmaxf(fmaxf(v0.z, v1.z), fmaxf(v2.z, v3.z)) + bb8[ol];
            s += fminf(fmaxf(m, -1.f), 1.f);
            m = fmaxf(fmaxf(v0.w, v1.w), fmaxf(v2.w, v3.w)) + bb8[ol];
            s += fminf(fmaxf(m, -1.f), 1.f);
            psum8[ol] += s;
        }
        __syncthreads();
    }

    // ---- per-tile reduction: reuse qbuf as scratch [64 oc][32 lanes] ----
    float* red2 = qbuf;
    #pragma unroll
    for (int ol = 0; ol < 8; ol++)
        red2[(wid * 8 + ol) * 32 + lane] = psum8[ol];
    __syncthreads();
    if (tid < 64) {
        const float4* r = (const float4*)(red2 + tid * 32);
        float4 s4 = make_float4(0.f, 0.f, 0.f, 0.f);
        #pragma unroll
        for (int k = 0; k < 8; k++) {
            float4 v = r[k];
            s4.x += v.x; s4.y += v.y; s4.z += v.z; s4.w += v.w;
        }
        float v = (s4.x + s4.y) + (s4.z + s4.w);
        asm volatile("st.global.cg.f32 [%0], %1;"
                     :: "l"(&g_part[b][tid][tile]), "f"(v) : "memory");
    }
    __syncthreads();

    // ---- last-CTA finalize: acq_rel atomic (no L1 flush), ld.cg reads ----
    if (tid == 0) {
        int old;
        asm volatile("atom.acq_rel.gpu.global.add.s32 %0, [%1], %2;"
                     : "=r"(old) : "l"(&g_count[b]), "r"(1) : "memory");
        s_last = (old == NTILE - 1);
    }
    __syncthreads();
    if (s_last) {
        if (tid < 64) {
            float s = 0.f;
            #pragma unroll
            for (int t = 0; t < NTILE; ++t)
                s += __ldcg(&g_part[b][tid][t]);
            out[b * C_ + tid] = tanhf(s * (1.0f / 4096.0f));
        }
        if (tid == 0) {
            int zero = 0;
            asm volatile("st.global.cg.s32 [%0], %1;" :: "l"(&g_count[b]), "r"(zero) : "memory");
        }
    }
}

extern "C" void kernel_launch(void* const* d_in, const int* in_sizes, int n_in,
                              void* d_out, int out_size)
{
    const float* x    = (const float*)d_in[0];
    const float* w    = (const float*)d_in[1];
    const float* bias = (const float*)d_in[2];
    float* out = (float*)d_out;

    cudaFuncSetAttribute(fused_hmma_kernel,
                         cudaFuncAttributeMaxDynamicSharedMemorySize, SMEM_TOTAL);

    prep_wfragB<<<64, 256>>>(w);
    fused_hmma_kernel<<<dim3(NTILE, B_), 256, SMEM_TOTAL>>>(x, bias, out);
}

// round 16
// speedup vs baseline: 1.0441x; 1.0437x over previous
#include <cuda_runtime.h>
#include <cuda_fp16.h>
#include <cstdint>
#include <math.h>

#define B_    32
#define C_    64
#define HW_   64
#define NTILE 16

// ---- smem layout ----
#define XS_HSTRIDE 72                        // halves per (R,px) row (144B)
#define XS_BYTES   (6*66*XS_HSTRIDE*2)       // 57024
#define QBUF_OFF   XS_BYTES
#define QPX        132                       // padded px stride (floats)
#define QBUF_BYTES (4*64*QPX*4)              // 135168
#define SMEM_TOTAL (QBUF_OFF + QBUF_BYTES)   // 192192

// fragment-ordered B (weight) table: [warpclass 8][frag 64 = (kt*4+j)*4+ng][lane 32]
__device__ uint2 g_wfragB[8][64][32];
__device__ float g_part[B_][C_][NTILE];

__device__ __forceinline__ void mma_xw(float* c, const uint4 a, const uint2 b) {
    asm volatile("mma.sync.aligned.m16n8k16.row.col.f32.f16.f16.f32 "
        "{%0,%1,%2,%3}, {%4,%5,%6,%7}, {%8,%9}, {%0,%1,%2,%3};"
        : "+f"(c[0]), "+f"(c[1]), "+f"(c[2]), "+f"(c[3])
        : "r"(a.x), "r"(a.y), "r"(a.z), "r"(a.w), "r"(b.x), "r"(b.y));
}
__device__ __forceinline__ void ldsm_x4(uint4& d, uint32_t addr) {
    asm volatile("ldmatrix.sync.aligned.m8n8.x4.shared.b16 {%0,%1,%2,%3}, [%4];"
        : "=r"(d.x), "=r"(d.y), "=r"(d.z), "=r"(d.w) : "r"(addr));
}
__device__ __forceinline__ uint32_t smem_u32(const void* p) {
    uint32_t a;
    asm("{ .reg .u64 t; cvta.to.shared.u64 t, %1; cvt.u32.u64 %0, t; }" : "=r"(a) : "l"(p));
    return a;
}

// ---- prep: w[ic][oc][kh][kw] fp32 -> B-fragment fp16 table ----
__global__ void prep_wfragB(const float* __restrict__ w) {
    int idx = blockIdx.x * 256 + threadIdx.x;            // 8*64*32 = 16384
    if (idx < 16384) {
        int wc = idx >> 11, f = (idx >> 5) & 63, t = idx & 31;
        int q = wc >> 1, h = wc & 1;
        int kt = f >> 4, j = (f >> 2) & 3, ng = f & 3;
        int jh = j >> 1, jw = j & 1;
        int a = q >> 1, bb = q & 1;
        int kh = a ? (jh ? 2 : 0) : (jh ? 3 : 1);
        int kw = bb ? (jw ? 2 : 0) : (jw ? 3 : 1);
        int tap = kh * 4 + kw;
        int oc = h * 32 + ng * 8 + (t >> 2);
        int k0 = kt * 16 + (t & 3) * 2;
        uint2 v;
        __half2 b0 = __floats2half2_rn(w[k0 * 1024 + oc * 16 + tap],
                                       w[(k0 + 1) * 1024 + oc * 16 + tap]);
        __half2 b1 = __floats2half2_rn(w[(k0 + 8) * 1024 + oc * 16 + tap],
                                       w[(k0 + 9) * 1024 + oc * 16 + tap]);
        v.x = *(uint32_t*)&b0;
        v.y = *(uint32_t*)&b1;
        g_wfragB[wc][f][t] = v;
    }
}

// ---- main fused kernel (PDL: overlaps with prep) ----
__global__ void __launch_bounds__(256, 1)
fused_hmma_kernel(const float* __restrict__ x, const float* __restrict__ bias)
{
    extern __shared__ char smem[];
    __half* xs   = (__half*)smem;                        // [6*66][72]
    float*  qbuf = (float*)(smem + QBUF_OFF);            // [4q][64oc][132px]
    const uint32_t xs_b = smem_u32(smem);

    const int tid  = threadIdx.x;
    const int lane = tid & 31;
    const int wid  = tid >> 5;
    const int tile = blockIdx.x;
    const int b    = blockIdx.y;
    const int pr0  = tile * 4;

    // ---- stage x slab as fp16 [R][px][ic] (independent of prep's output) ----
    const float* xb = x + (size_t)b * C_ * HW_ * HW_;
    for (int ri = tid; ri < 384; ri += 256) {            // 6 rows * 64 ic
        int R = ri >> 6, ic = ri & 63, ih = pr0 - 1 + R;
        __half hv[66];
        #pragma unroll
        for (int p = 0; p < 66; p++) hv[p] = __float2half(0.f);
        if (ih >= 0 && ih < HW_) {
            const float4* src = (const float4*)(xb + ((size_t)ic * HW_ + ih) * HW_);
            #pragma unroll
            for (int p = 0; p < 16; p++) {
                float4 v = src[p];
                hv[1 + 4*p] = __float2half(v.x);
                hv[2 + 4*p] = __float2half(v.y);
                hv[3 + 4*p] = __float2half(v.z);
                hv[4 + 4*p] = __float2half(v.w);
            }
        }
        #pragma unroll
        for (int p = 0; p < 66; p++)
            xs[(R * 66 + p) * XS_HSTRIDE + ic] = hv[p];
    }

    // ---- wait for prep grid to fully complete, then load fragments ----
    cudaGridDependencySynchronize();

    uint2 Bw[64];
    #pragma unroll
    for (int f = 0; f < 64; f++) Bw[f] = g_wfragB[wid][f][lane];
    __syncthreads();

    const int q = wid >> 1, h = wid & 1;
    const int a = q >> 1, bb = q & 1;
    const int ro[2] = { a ? 2 : 1, a ? 1 : 0 };          // jh = 0,1
    const int co[2] = { bb ? 2 : 1, bb ? 1 : 0 };        // jw = 0,1

    const int mblk = (lane >> 3) & 1;
    const int kblk = lane >> 4;
    const int lrow = lane & 7;

    float bb8[8], psum8[8];
    #pragma unroll
    for (int ol = 0; ol < 8; ol++) { bb8[ol] = bias[wid * 8 + ol]; psum8[ol] = 0.f; }

    for (int hf = 0; hf < 2; hf++) {
        // ---- mainloop: 8 n-tiles of 16 px covering 2 pooled rows x 64 px ----
        #pragma unroll 2
        for (int nt = 0; nt < 8; nt++) {
            const int lr  = hf * 2 + (nt >> 2);
            const int pc0 = (nt & 3) * 16;

            uint4 Af[4][4];
            #pragma unroll
            for (int j = 0; j < 4; j++) {
                int R  = lr + ro[j >> 1];
                int px = pc0 + co[j & 1] + mblk * 8 + lrow;
                uint32_t rowbase = xs_b +
                    (((R * 66 + px) * XS_HSTRIDE) + kblk * 8) * 2;
                #pragma unroll
                for (int kt = 0; kt < 4; kt++)
                    ldsm_x4(Af[j][kt], rowbase + kt * 32);
            }

            float acc[4][4];
            #pragma unroll
            for (int ng = 0; ng < 4; ng++)
                #pragma unroll
                for (int i = 0; i < 4; i++) acc[ng][i] = 0.f;

            #pragma unroll
            for (int kt = 0; kt < 4; kt++)
                #pragma unroll
                for (int j = 0; j < 4; j++)
                    #pragma unroll
                    for (int ng = 0; ng < 4; ng++)
                        mma_xw(acc[ng], Af[j][kt], Bw[(kt * 4 + j) * 4 + ng]);

            int pxh = (nt >> 2) * 64 + pc0 + (lane >> 2);
            int ocb = h * 32 + 2 * (lane & 3);
            #pragma unroll
            for (int ng = 0; ng < 4; ng++) {
                float* d = qbuf + (q * 64 + ocb + ng * 8) * QPX + pxh;
                d[0]       = acc[ng][0];
                d[QPX]     = acc[ng][1];
                d[8]       = acc[ng][2];
                d[QPX + 8] = acc[ng][3];
            }
        }
        __syncthreads();

        // ---- epilogue: warp w owns oc rows w*8..w*8+7; lane reads px lane*4..+3 ----
        #pragma unroll
        for (int ol = 0; ol < 8; ol++) {
            int oc = wid * 8 + ol;
            const float* base = qbuf + oc * QPX + lane * 4;
            float4 v0 = *(const float4*)(base + 0 * 64 * QPX);
            float4 v1 = *(const float4*)(base + 1 * 64 * QPX);
            float4 v2 = *(const float4*)(base + 2 * 64 * QPX);
            float4 v3 = *(const float4*)(base + 3 * 64 * QPX);
            float m, s = 0.f;
            m = fmaxf(fmaxf(v0.x, v1.x), fmaxf(v2.x, v3.x)) + bb8[ol];
            s += fminf(fmaxf(m, -1.f), 1.f);
            m = fmaxf(fmaxf(v0.y, v1.y), fmaxf(v2.y, v3.y)) + bb8[ol];
            s += fminf(fmaxf(m, -1.f), 1.f);
            m = fmaxf(fmaxf(v0.z, v1.z), fmaxf(v2.z, v3.z)) + bb8[ol];
            s += fminf(fmaxf(m, -1.f), 1.f);
            m = fmaxf(fmaxf(v0.w, v1.w), fmaxf(v2.w, v3.w)) + bb8[ol];
            s += fminf(fmaxf(m, -1.f), 1.f);
            psum8[ol] += s;
        }
        __syncthreads();
    }

    // ---- reduction: reuse qbuf as scratch [64 oc][32 lanes] ----
    float* red2 = qbuf;
    #pragma unroll
    for (int ol = 0; ol < 8; ol++)
        red2[(wid * 8 + ol) * 32 + lane] = psum8[ol];
    __syncthreads();
    if (tid < 64) {
        const float4* r = (const float4*)(red2 + tid * 32);
        float4 s4 = make_float4(0.f, 0.f, 0.f, 0.f);
        #pragma unroll
        for (int k = 0; k < 8; k++) {
            float4 v = r[k];
            s4.x += v.x; s4.y += v.y; s4.z += v.z; s4.w += v.w;
        }
        g_part[b][tid][tile] = (s4.x + s4.y) + (s4.z + s4.w);
    }
}

// ---- finalize (PDL: launches early, waits for main grid) ----
__global__ void finalize_kernel(float* __restrict__ out)
{
    cudaGridDependencySynchronize();
    int b  = blockIdx.x;
    int oc = threadIdx.x;
    float s = 0.f;
    #pragma unroll
    for (int t = 0; t < NTILE; ++t) s += g_part[b][oc][t];
    out[b * C_ + oc] = tanhf(s * (1.0f / 4096.0f));
}

extern "C" void kernel_launch(void* const* d_in, const int* in_sizes, int n_in,
                              void* d_out, int out_size)
{
    const float* x    = (const float*)d_in[0];
    const float* w    = (const float*)d_in[1];
    const float* bias = (const float*)d_in[2];
    float* out = (float*)d_out;

    cudaFuncSetAttribute(fused_hmma_kernel,
                         cudaFuncAttributeMaxDynamicSharedMemorySize, SMEM_TOTAL);

    // prep: normal launch
    prep_wfragB<<<64, 256>>>(w);

    cudaLaunchAttribute attrs[1];
    attrs[0].id = cudaLaunchAttributeProgrammaticStreamSerialization;
    attrs[0].val.programmaticStreamSerializationAllowed = 1;

    // main: PDL overlap with prep
    {
        cudaLaunchConfig_t cfg = {};
        cfg.gridDim  = dim3(NTILE, B_);
        cfg.blockDim = dim3(256);
        cfg.dynamicSmemBytes = SMEM_TOTAL;
        cfg.stream = 0;
        cfg.attrs = attrs;
        cfg.numAttrs = 1;
        cudaLaunchKernelEx(&cfg, fused_hmma_kernel, x, bias);
    }

    // finalize: PDL overlap with main tail
    {
        cudaLaunchConfig_t cfg = {};
        cfg.gridDim  = dim3(B_);
        cfg.blockDim = dim3(C_);
        cfg.dynamicSmemBytes = 0;
        cfg.stream = 0;
        cfg.attrs = attrs;
        cfg.numAttrs = 1;
        cudaLaunchKernelEx(&cfg, finalize_kernel, out);
    }
}

// round 17
// speedup vs baseline: 1.0907x; 1.0447x over previous
#include <cuda_runtime.h>
#include <cuda_fp16.h>
#include <cstdint>
#include <math.h>

#define B_    32
#define C_    64
#define HW_   64
#define NTILE 32                             // half-tiles: 2 pooled rows each
#define NUNITS (B_ * NTILE)                  // 1024
#define GRID_P 148                           // persistent CTAs

// ---- smem layout ----
#define XS_HSTRIDE 72                        // halves per (R,px) row (144B)
#define XS_BYTES   (4*66*XS_HSTRIDE*2)       // 38016 (4 input rows)
#define QBUF_OFF   XS_BYTES
#define QPX        132                       // padded px stride (floats)
#define QBUF_BYTES (4*64*QPX*4)              // 135168
#define SMEM_TOTAL (QBUF_OFF + QBUF_BYTES)   // 173184

// fragment-ordered B (weight) table: [warpclass 8][frag 64 = (kt*4+j)*4+ng][lane 32]
__device__ uint2 g_wfragB[8][64][32];
__device__ float g_part[B_][C_][NTILE];

__device__ __forceinline__ void mma_xw(float* c, const uint4 a, const uint2 b) {
    asm volatile("mma.sync.aligned.m16n8k16.row.col.f32.f16.f16.f32 "
        "{%0,%1,%2,%3}, {%4,%5,%6,%7}, {%8,%9}, {%0,%1,%2,%3};"
        : "+f"(c[0]), "+f"(c[1]), "+f"(c[2]), "+f"(c[3])
        : "r"(a.x), "r"(a.y), "r"(a.z), "r"(a.w), "r"(b.x), "r"(b.y));
}
__device__ __forceinline__ void ldsm_x4(uint4& d, uint32_t addr) {
    asm volatile("ldmatrix.sync.aligned.m8n8.x4.shared.b16 {%0,%1,%2,%3}, [%4];"
        : "=r"(d.x), "=r"(d.y), "=r"(d.z), "=r"(d.w) : "r"(addr));
}
__device__ __forceinline__ uint32_t smem_u32(const void* p) {
    uint32_t a;
    asm("{ .reg .u64 t; cvta.to.shared.u64 t, %1; cvt.u32.u64 %0, t; }" : "=r"(a) : "l"(p));
    return a;
}

// ---- prep: w[ic][oc][kh][kw] fp32 -> B-fragment fp16 table ----
__global__ void prep_wfragB(const float* __restrict__ w) {
    int idx = blockIdx.x * 256 + threadIdx.x;            // 8*64*32 = 16384
    if (idx < 16384) {
        int wc = idx >> 11, f = (idx >> 5) & 63, t = idx & 31;
        int q = wc >> 1, h = wc & 1;
        int kt = f >> 4, j = (f >> 2) & 3, ng = f & 3;
        int jh = j >> 1, jw = j & 1;
        int a = q >> 1, bb = q & 1;
        int kh = a ? (jh ? 2 : 0) : (jh ? 3 : 1);
        int kw = bb ? (jw ? 2 : 0) : (jw ? 3 : 1);
        int tap = kh * 4 + kw;
        int oc = h * 32 + ng * 8 + (t >> 2);
        int k0 = kt * 16 + (t & 3) * 2;
        uint2 v;
        __half2 b0 = __floats2half2_rn(w[k0 * 1024 + oc * 16 + tap],
                                       w[(k0 + 1) * 1024 + oc * 16 + tap]);
        __half2 b1 = __floats2half2_rn(w[(k0 + 8) * 1024 + oc * 16 + tap],
                                       w[(k0 + 9) * 1024 + oc * 16 + tap]);
        v.x = *(uint32_t*)&b0;
        v.y = *(uint32_t*)&b1;
        g_wfragB[wc][f][t] = v;
    }
}

// ---- stage one unit's x slab: rows pr0-1..pr0+2 as fp16 [R][px][ic] ----
__device__ __forceinline__ void stage_unit(__half* xs, const float* __restrict__ x,
                                           int b, int ht, int tid)
{
    const int pr0 = ht * 2;
    const float* xb = x + (size_t)b * C_ * HW_ * HW_;
    if (tid < 256) {                                     // 4 rows * 64 ic
        int R = tid >> 6, ic = tid & 63, ih = pr0 - 1 + R;
        __half hv[66];
        #pragma unroll
        for (int p = 0; p < 66; p++) hv[p] = __float2half(0.f);
        if (ih >= 0 && ih < HW_) {
            const float4* src = (const float4*)(xb + ((size_t)ic * HW_ + ih) * HW_);
            #pragma unroll
            for (int p = 0; p < 16; p++) {
                float4 v = src[p];
                hv[1 + 4*p] = __float2half(v.x);
                hv[2 + 4*p] = __float2half(v.y);
                hv[3 + 4*p] = __float2half(v.z);
                hv[4 + 4*p] = __float2half(v.w);
            }
        }
        #pragma unroll
        for (int p = 0; p < 66; p++)
            xs[(R * 66 + p) * XS_HSTRIDE + ic] = hv[p];
    }
}

// ---- main persistent kernel (PDL: overlaps with prep) ----
__global__ void __launch_bounds__(256, 1)
fused_hmma_kernel(const float* __restrict__ x, const float* __restrict__ bias)
{
    extern __shared__ char smem[];
    __half* xs   = (__half*)smem;                        // [4*66][72]
    float*  qbuf = (float*)(smem + QBUF_OFF);            // [4q][64oc][132px]
    const uint32_t xs_b = smem_u32(smem);

    const int tid  = threadIdx.x;
    const int lane = tid & 31;
    const int wid  = tid >> 5;
    const int cta  = blockIdx.x;

    // ---- stage first unit while prep may still be running ----
    int u0 = cta;
    {
        int b = u0 >> 5, ht = u0 & 31;
        stage_unit(xs, x, b, ht, tid);
    }

    // ---- wait for prep grid, then load fragments + bias ----
    cudaGridDependencySynchronize();

    uint2 Bw[64];
    #pragma unroll
    for (int f = 0; f < 64; f++) Bw[f] = g_wfragB[wid][f][lane];

    float bb8[8];
    #pragma unroll
    for (int ol = 0; ol < 8; ol++) bb8[ol] = bias[wid * 8 + ol];

    const int q = wid >> 1, h = wid & 1;
    const int a = q >> 1, bb = q & 1;
    const int ro[2] = { a ? 2 : 1, a ? 1 : 0 };          // jh = 0,1
    const int co[2] = { bb ? 2 : 1, bb ? 1 : 0 };        // jw = 0,1

    const int mblk = (lane >> 3) & 1;
    const int kblk = lane >> 4;
    const int lrow = lane & 7;

    __syncthreads();

    for (int u = u0; u < NUNITS; u += GRID_P) {
        const int b  = u >> 5;
        const int ht = u & 31;

        // ---- mainloop: 8 n-tiles of 16 px covering 2 pooled rows x 64 px ----
        #pragma unroll 2
        for (int nt = 0; nt < 8; nt++) {
            const int lr  = nt >> 2;                     // pooled row 0/1
            const int pc0 = (nt & 3) * 16;

            uint4 Af[4][4];
            #pragma unroll
            for (int j = 0; j < 4; j++) {
                int R  = lr + ro[j >> 1];
                int px = pc0 + co[j & 1] + mblk * 8 + lrow;
                uint32_t rowbase = xs_b +
                    (((R * 66 + px) * XS_HSTRIDE) + kblk * 8) * 2;
                #pragma unroll
                for (int kt = 0; kt < 4; kt++)
                    ldsm_x4(Af[j][kt], rowbase + kt * 32);
            }

            float acc[4][4];
            #pragma unroll
            for (int ng = 0; ng < 4; ng++)
                #pragma unroll
                for (int i = 0; i < 4; i++) acc[ng][i] = 0.f;

            #pragma unroll
            for (int kt = 0; kt < 4; kt++)
                #pragma unroll
                for (int j = 0; j < 4; j++)
                    #pragma unroll
                    for (int ng = 0; ng < 4; ng++)
                        mma_xw(acc[ng], Af[j][kt], Bw[(kt * 4 + j) * 4 + ng]);

            int pxh = lr * 64 + pc0 + (lane >> 2);
            int ocb = h * 32 + 2 * (lane & 3);
            #pragma unroll
            for (int ng = 0; ng < 4; ng++) {
                float* d = qbuf + (q * 64 + ocb + ng * 8) * QPX + pxh;
                d[0]       = acc[ng][0];
                d[QPX]     = acc[ng][1];
                d[8]       = acc[ng][2];
                d[QPX + 8] = acc[ng][3];
            }
        }
        __syncthreads();

        // ---- epilogue: warp w owns oc rows w*8..w*8+7; lane reads px lane*4..+3 ----
        float psum8[8];
        #pragma unroll
        for (int ol = 0; ol < 8; ol++) {
            int oc = wid * 8 + ol;
            const float* base = qbuf + oc * QPX + lane * 4;
            float4 v0 = *(const float4*)(base + 0 * 64 * QPX);
            float4 v1 = *(const float4*)(base + 1 * 64 * QPX);
            float4 v2 = *(const float4*)(base + 2 * 64 * QPX);
            float4 v3 = *(const float4*)(base + 3 * 64 * QPX);
            float m, s = 0.f;
            m = fmaxf(fmaxf(v0.x, v1.x), fmaxf(v2.x, v3.x)) + bb8[ol];
            s += fminf(fmaxf(m, -1.f), 1.f);
            m = fmaxf(fmaxf(v0.y, v1.y), fmaxf(v2.y, v3.y)) + bb8[ol];
            s += fminf(fmaxf(m, -1.f), 1.f);
            m = fmaxf(fmaxf(v0.z, v1.z), fmaxf(v2.z, v3.z)) + bb8[ol];
            s += fminf(fmaxf(m, -1.f), 1.f);
            m = fmaxf(fmaxf(v0.w, v1.w), fmaxf(v2.w, v3.w)) + bb8[ol];
            s += fminf(fmaxf(m, -1.f), 1.f);
            psum8[ol] = s;
        }
        __syncthreads();

        // ---- per-unit reduction: reuse qbuf as scratch [64 oc][32 lanes] ----
        float* red2 = qbuf;
        #pragma unroll
        for (int ol = 0; ol < 8; ol++)
            red2[(wid * 8 + ol) * 32 + lane] = psum8[ol];
        __syncthreads();
        if (tid < 64) {
            const float4* r = (const float4*)(red2 + tid * 32);
            float4 s4 = make_float4(0.f, 0.f, 0.f, 0.f);
            #pragma unroll
            for (int k = 0; k < 8; k++) {
                float4 v = r[k];
                s4.x += v.x; s4.y += v.y; s4.z += v.z; s4.w += v.w;
            }
            g_part[b][tid][ht] = (s4.x + s4.y) + (s4.z + s4.w);
        }
        __syncthreads();                                 // qbuf + xs free

        // ---- stage next unit ----
        int un = u + GRID_P;
        if (un < NUNITS)
            stage_unit(xs, x, un >> 5, un & 31, tid);
        __syncthreads();
    }
}

// ---- finalize (PDL: launches early, waits for main grid) ----
__global__ void finalize_kernel(float* __restrict__ out)
{
    cudaGridDependencySynchronize();
    int b  = blockIdx.x;
    int oc = threadIdx.x;
    float s = 0.f;
    #pragma unroll
    for (int t = 0; t < NTILE; ++t) s += g_part[b][oc][t];
    out[b * C_ + oc] = tanhf(s * (1.0f / 4096.0f));
}

extern "C" void kernel_launch(void* const* d_in, const int* in_sizes, int n_in,
                              void* d_out, int out_size)
{
    const float* x    = (const float*)d_in[0];
    const float* w    = (const float*)d_in[1];
    const float* bias = (const float*)d_in[2];
    float* out = (float*)d_out;

    cudaFuncSetAttribute(fused_hmma_kernel,
                         cudaFuncAttributeMaxDynamicSharedMemorySize, SMEM_TOTAL);

    // prep: normal launch
    prep_wfragB<<<64, 256>>>(w);

    cudaLaunchAttribute attrs[1];
    attrs[0].id = cudaLaunchAttributeProgrammaticStreamSerialization;
    attrs[0].val.programmaticStreamSerializationAllowed = 1;

    // main: persistent, PDL overlap with prep
    {
        cudaLaunchConfig_t cfg = {};
        cfg.gridDim  = dim3(GRID_P);
        cfg.blockDim = dim3(256);
        cfg.dynamicSmemBytes = SMEM_TOTAL;
        cfg.stream = 0;
        cfg.attrs = attrs;
        cfg.numAttrs = 1;
        cudaLaunchKernelEx(&cfg, fused_hmma_kernel, x, bias);
    }

    // finalize: PDL overlap with main tail
    {
        cudaLaunchConfig_t cfg = {};
        cfg.gridDim  = dim3(B_);
        cfg.blockDim = dim3(C_);
        cfg.dynamicSmemBytes = 0;
        cfg.stream = 0;
        cfg.attrs = attrs;
        cfg.numAttrs = 1;
        cudaLaunchKernelEx(&cfg, finalize_kernel, out);
    }
}